// round 11
// baseline (speedup 1.0000x reference)
#include <cuda_runtime.h>
#include <cuda_bf16.h>

#define P_LVL 16
#define B_DIM 64
#define T_DIM 512
#define NS 48
#define NS2 (NS*NS)
#define LN2 0.6931471805599453

// ---- packed f32x2 helpers (FFMA2 path, PTX-only per SASS_QUICKREF) ----
#define FMA2(acc, a, b) asm("fma.rn.f32x2 %0, %1, %2, %0;" : "+l"(acc) : "l"(a), "l"(b))
#define ADD2(d, a, b)   asm("add.rn.f32x2 %0, %1, %2;"      : "=l"(d)  : "l"(a), "l"(b))
#define PACK2(d, lo, hi) asm("mov.b64 %0, {%1, %2};"        : "=l"(d)  : "f"(lo), "f"(hi))
#define UNPK2(lo, hi, v) asm("mov.b64 {%0, %1}, %2;"        : "=f"(lo), "=f"(hi) : "l"(v))

__device__ __align__(16) float g_llT[P_LVL * B_DIM];   // 1024
__device__ __align__(16) float g_llL[T_DIM * B_DIM];   // 32768
__device__ __align__(16) float g_llR[T_DIM * B_DIM];   // 32768

struct Smem {
    union {
        float trans[NS2];              // mode 0: persistent (score gathers)
        float em[4][P_LVL][NS];        // modes 1/2: staged exp(emissions), 4 seqs
    };
    float u[2][4][NS];                 // double-buffered alpha (up to 4 seqs)
    float sc[4][NS];                   // score partials / per-step scores
};

// Grid layout (48-thread blocks; one group per block):
//   [0, 512)          mode 0 (time axis):   2 seqs/block (sids 2b, 2b+1)
//   [512, 4608)       mode 1 (level axis):  2 jobs x 4 seqs
//   [4608, 8704)      mode 2 (rolled):      2 jobs x 4 seqs
// All sids in a block share one p (mode 0) / one t (modes 1/2) -> uniform len.
__global__ __launch_bounds__(NS, 12) void crf_fwd_kernel(
    const float* __restrict__ logits,
    const float* __restrict__ trT,
    const float* __restrict__ trL,
    const float* __restrict__ trR,
    const int*   __restrict__ tags)
{
    __shared__ Smem sm;
    const int j = threadIdx.x;           // state 0..47

    const int bid = blockIdx.x;
    int mode, mbase;
    const float* traw;
    float* outp;
    if (bid < 512)       { mode = 0; mbase = bid;                traw = trT; outp = g_llT; }
    else if (bid < 4608) { mode = 1; mbase = (bid - 512) * 2;    traw = trL; outp = g_llL; }
    else                 { mode = 2; mbase = (bid - 4608) * 2;   traw = trR; outp = g_llR; }

    // trans -> smem (coalesced), build Epk; modes 1/2 then reuse that smem.
    for (int k = j; k < NS2; k += NS) sm.trans[k] = traw[k];
    __syncthreads();
    unsigned long long Epk[NS / 2];
#pragma unroll
    for (int k = 0; k < NS / 2; k++) {
        float lo = __expf(sm.trans[(2 * k) * NS + j]);
        float hi = __expf(sm.trans[(2 * k + 1) * NS + j]);
        PACK2(Epk[k], lo, hi);
    }
    __syncthreads();

    if (mode == 0) {
        // ---- mode 0: 2 seqs, sids 2*bid + {0,1}; exp(emit) in prefetch ring ----
        const int sidA = 2 * mbase;
        const int p = sidA >> 6;
        const int len = T_DIM - p;
        const int baseA = sidA * (T_DIM * NS);
        const int baseB = baseA + T_DIM * NS;
        const int* tgA = tags + sidA * T_DIM;
        const int* tgB = tgA + T_DIM;

        float spA = 0.f, spB = 0.f;
        for (int t = j; t < len; t += NS) {
            int a0 = tgA[t];
            int b0 = tgB[t];
            spA += logits[baseA + t * NS + a0];
            spB += logits[baseB + t * NS + b0];
            if (t + 1 < len) {
                spA += sm.trans[a0 * NS + tgA[t + 1]];
                spB += sm.trans[b0 * NS + tgB[t + 1]];
            }
        }

        const float* epA = logits + baseA + j;
        const float* epB = logits + baseB + j;
        sm.u[0][0][j] = __expf(epA[0]);
        sm.u[0][1][j] = __expf(epB[0]);

        float cA[4], cB[4];                 // ring holds exp(emit)
#pragma unroll
        for (int k = 0; k < 4; k++) {
            int tl = min(1 + k, len - 1);
            cA[k] = __expf(epA[tl * NS]);
            cB[k] = __expf(epB[tl * NS]);
        }
        int CexpA = 0, CexpB = 0, cur = 0;
        __syncthreads();

        for (int t0 = 1; t0 < len; t0 += 4) {
            float nA[4], nB[4];
#pragma unroll
            for (int k = 0; k < 4; k++) {
                int tl = min(t0 + 4 + k, len - 1);
                nA[k] = __expf(epA[tl * NS]);
                nB[k] = __expf(epB[tl * NS]);
            }
#pragma unroll
            for (int k = 0; k < 4; k++) {
                if (t0 + k < len) {   // block-uniform predicate
                    const ulonglong2* wA2 = reinterpret_cast<const ulonglong2*>(sm.u[cur][0]);
                    const ulonglong2* wB2 = reinterpret_cast<const ulonglong2*>(sm.u[cur][1]);
                    unsigned long long a0 = 0ull, a1 = 0ull, b0 = 0ull, b1 = 0ull;
                    ulonglong2 va0 = wA2[0];
                    ulonglong2 vb0 = wB2[0];
                    FMA2(a0, va0.x, Epk[0]); FMA2(a1, va0.y, Epk[1]);
                    FMA2(b0, vb0.x, Epk[0]); FMA2(b1, vb0.y, Epk[1]);
#pragma unroll
                    for (int q = 1; q < 12; q++) {
                        ulonglong2 va = wA2[q];
                        ulonglong2 vb = wB2[q];
                        FMA2(a0, va.x, Epk[2 * q]); FMA2(a1, va.y, Epk[2 * q + 1]);
                        FMA2(b0, vb.x, Epk[2 * q]); FMA2(b1, vb.y, Epk[2 * q + 1]);
                    }
                    unsigned long long as, bs;
                    ADD2(as, a0, a1); ADD2(bs, b0, b1);
                    float alo, ahi, blo, bhi;
                    UNPK2(alo, ahi, as); UNPK2(blo, bhi, bs);
                    unsigned int eA = ((unsigned int)va0.x) >> 23;
                    unsigned int eB = ((unsigned int)vb0.x) >> 23;
                    CexpA += (int)eA - 127;
                    CexpB += (int)eB - 127;
                    float sA = __uint_as_float((254u - eA) << 23);
                    float sB = __uint_as_float((254u - eB) << 23);
                    sm.u[cur ^ 1][0][j] = (alo + ahi) * (cA[k] * sA);
                    sm.u[cur ^ 1][1][j] = (blo + bhi) * (cB[k] * sB);
                    __syncthreads();
                    cur ^= 1;
                }
            }
#pragma unroll
            for (int k = 0; k < 4; k++) { cA[k] = nA[k]; cB[k] = nB[k]; }
        }

        sm.sc[0][j] = spA;
        sm.sc[1][j] = spB;
        __syncthreads();
        if (j < 16) {
            sm.sc[0][j] += sm.sc[0][j + 16] + sm.sc[0][j + 32];
            sm.sc[1][j] += sm.sc[1][j + 16] + sm.sc[1][j + 32];
            float* uA = sm.u[cur][0];
            float* uB = sm.u[cur][1];
            uA[j] += uA[j + 16] + uA[j + 32];
            uB[j] += uB[j + 16] + uB[j + 32];
        }
        __syncthreads();
        if (j < 2) {
            const float* uf = sm.u[cur][j];
            const float* sf = sm.sc[j];
            float su = 0.f, sc = 0.f;
#pragma unroll
            for (int i = 0; i < 16; i++) { su += uf[i]; sc += sf[i]; }
            int Ce = (j == 0) ? CexpA : CexpB;
            outp[sidA + j] = (float)((double)sc - ((double)logf(su) + (double)Ce * LN2));
        }
        return;
    }

    // ---- modes 1/2: 4 seqs per job, 2 jobs of sids 4m..4m+3 ----
    const int SEQ_STRIDE = T_DIM * NS;
    for (int it = 0; it < 2; ++it) {
        const int m    = mbase + it;
        const int sid0 = 4 * m;
        const int t    = sid0 >> 6;           // uniform across the 4 sids
        int estride, tstride, len;
        if (mode == 1) {
            estride = B_DIM * T_DIM * NS;
            tstride = B_DIM * T_DIM;
            len     = min(P_LVL, T_DIM - t);
        } else {
            estride = B_DIM * T_DIM * NS - NS;
            tstride = B_DIM * T_DIM - 1;
            len     = min(P_LVL, t + 1);
        }
        const int b0    = sid0 & 63;
        const int baseG = (b0 * T_DIM + t) * NS;

        // stage exp(emissions) (own state) for 4 seqs: 64 LDGs + 64 MUFU,
        // all MLP-rich; the step loop then has no MUFU at all.
#pragma unroll
        for (int s = 0; s < 4; s++) {
#pragma unroll
            for (int k = 0; k < P_LVL; k++) {
                int kk = min(k, len - 1);
                sm.em[s][k][j] = __expf(logits[baseG + s * SEQ_STRIDE + kk * estride + j]);
            }
        }

        // score phase: 64 slots (4 seqs x 16 steps) over 48 threads, 2 rounds
#pragma unroll
        for (int r = 0; r < 2; r++) {
            int slot = j + r * NS;
            if (slot < 64) {
                int sl = slot >> 4;
                int tt = slot & 15;
                float sp = 0.f;
                if (tt < len) {
                    int bb = b0 + sl;
                    int tb = bb * T_DIM + t;
                    int eb = (bb * T_DIM + t) * NS;
                    int tg0 = tags[tb + tt * tstride];
                    sp = logits[eb + tt * estride + tg0];
                    if (tt + 1 < len) {
                        int tg1 = tags[tb + (tt + 1) * tstride];
                        sp += traw[tg0 * NS + tg1];   // L2-cached gather
                    }
                }
                sm.sc[sl][tt] = sp;
            }
        }

#pragma unroll
        for (int s = 0; s < 4; s++)
            sm.u[0][s][j] = sm.em[s][0][j];   // already exp()

        int Cexp[4] = {0, 0, 0, 0};
        int cur = 0;
        __syncthreads();

        for (int tt = 1; tt < len; tt++) {
            unsigned long long acc0[4], acc1[4];
            unsigned int ue[4];
#pragma unroll
            for (int s = 0; s < 4; s++) {
                const ulonglong2* w2 = reinterpret_cast<const ulonglong2*>(sm.u[cur][s]);
                unsigned long long a0 = 0ull, a1 = 0ull;
                ulonglong2 v0 = w2[0];
                ue[s] = ((unsigned int)v0.x) >> 23;
                FMA2(a0, v0.x, Epk[0]); FMA2(a1, v0.y, Epk[1]);
#pragma unroll
                for (int k = 1; k < 12; k++) {
                    ulonglong2 v = w2[k];
                    FMA2(a0, v.x, Epk[2 * k]); FMA2(a1, v.y, Epk[2 * k + 1]);
                }
                acc0[s] = a0; acc1[s] = a1;
            }
#pragma unroll
            for (int s = 0; s < 4; s++) {
                unsigned long long as;
                ADD2(as, acc0[s], acc1[s]);
                float lo, hi;
                UNPK2(lo, hi, as);
                Cexp[s] += (int)ue[s] - 127;
                float sscl = __uint_as_float((254u - ue[s]) << 23);
                sm.u[cur ^ 1][s][j] = (lo + hi) * (sm.em[s][tt][j] * sscl);
            }
            __syncthreads();       // one barrier per 4 seq-steps, 1.5 warps only
            cur ^= 1;
        }

        __syncthreads();   // covers len==1 (score writes -> epilogue reads)
#pragma unroll
        for (int s = 0; s < 4; s++)
            if (j < 16) {
                float* uu = sm.u[cur][s];
                uu[j] += uu[j + 16] + uu[j + 32];
            }
        __syncthreads();
        if (j < 4) {
            const int s = j;
            const float* uf = sm.u[cur][s];
            const float* sf = sm.sc[s];
            float su = 0.f, sc = 0.f;
#pragma unroll
            for (int i = 0; i < 16; i++) { su += uf[i]; sc += sf[i]; }
            outp[sid0 + s] =
                (float)((double)sc - ((double)logf(su) + (double)Cexp[s] * LN2));
        }
        __syncthreads();   // protect smem reuse by next job
    }
}

// Deterministic reduction: fp32 partial chains (FP64 throughput on B300 is the
// bottleneck otherwise), double only in the fixed 256-wide tree.
__global__ void reduce_kernel(float* __restrict__ out) {
    __shared__ double sd[256];
    const int which = blockIdx.x;
    const float* src = (which == 0) ? g_llT : (which == 1) ? g_llL : g_llR;
    const int n4 = ((which == 0) ? (P_LVL * B_DIM) : (T_DIM * B_DIM)) / 4;
    const float4* s4 = reinterpret_cast<const float4*>(src);
    float a0 = 0.f, a1 = 0.f, a2 = 0.f, a3 = 0.f;
    for (int i = threadIdx.x; i < n4; i += 256) {
        float4 v = s4[i];
        a0 += v.x; a1 += v.y; a2 += v.z; a3 += v.w;
    }
    sd[threadIdx.x] = (double)(a0 + a1) + (double)(a2 + a3);
    __syncthreads();
    for (int s = 128; s > 0; s >>= 1) {
        if (threadIdx.x < s) sd[threadIdx.x] += sd[threadIdx.x + s];
        __syncthreads();
    }
    if (threadIdx.x == 0) out[which] = (float)(-sd[0]);
}

extern "C" void kernel_launch(void* const* d_in, const int* in_sizes, int n_in,
                              void* d_out, int out_size) {
    const float* logits = (const float*)d_in[0];
    const float* trT    = (const float*)d_in[1];
    const float* trL    = (const float*)d_in[2];
    const float* trR    = (const float*)d_in[3];
    const int*   tags   = (const int*)d_in[4];
    // d_in[5] = mask: analytic (t < T - p), not read.

    crf_fwd_kernel<<<512 + 4096 + 4096, NS>>>(logits, trT, trL, trR, tags);

    reduce_kernel<<<3, 256>>>((float*)d_out);
}

// round 13
// speedup vs baseline: 1.1461x; 1.1461x over previous
#include <cuda_runtime.h>
#include <cuda_bf16.h>

#define P_LVL 16
#define B_DIM 64
#define T_DIM 512
#define NS 48
#define NS2 (NS*NS)
#define GRP 2
#define LN2 0.6931471805599453

// ---- packed f32x2 helpers (FFMA2 path, PTX-only per SASS_QUICKREF) ----
#define FMA2(acc, a, b) asm("fma.rn.f32x2 %0, %1, %2, %0;" : "+l"(acc) : "l"(a), "l"(b))
#define ADD2(d, a, b)   asm("add.rn.f32x2 %0, %1, %2;"      : "=l"(d)  : "l"(a), "l"(b))
#define PACK2(d, lo, hi) asm("mov.b64 %0, {%1, %2};"        : "=l"(d)  : "f"(lo), "f"(hi))
#define UNPK2(lo, hi, v) asm("mov.b64 {%0, %1}, %2;"        : "=f"(lo), "=f"(hi) : "l"(v))

__device__ __align__(16) float g_llT[P_LVL * B_DIM];   // 1024
__device__ __align__(16) float g_llL[T_DIM * B_DIM];   // 32768
__device__ __align__(16) float g_llR[T_DIM * B_DIM];   // 32768

struct Smem {
    union {
        float trans[NS2];                 // mode 0: persistent (score gathers)
        float em[GRP][4][P_LVL][NS];      // modes 1/2: staged exp(emissions)
    };
    float u[2][GRP][4][NS];               // double-buffered alpha
    float sc[GRP][4][NS];                 // score partials
};

// 2-seq step (mode 0). Lane j owns state j; power-of-two renorm by u0.
// emA/emB are PRE-EXPONENTIATED emissions (exp hoisted off the critical path).
__device__ __forceinline__ void crf_step2(
    const float* __restrict__ wA, const float* __restrict__ wB,
    float* __restrict__ oA, float* __restrict__ oB,
    const unsigned long long* __restrict__ Epk,
    float emA, float emB, int j, int& CexpA, int& CexpB)
{
    const ulonglong2* wA2 = reinterpret_cast<const ulonglong2*>(wA);
    const ulonglong2* wB2 = reinterpret_cast<const ulonglong2*>(wB);
    unsigned long long a0 = 0ull, a1 = 0ull, b0 = 0ull, b1 = 0ull;
    ulonglong2 va0 = wA2[0];
    ulonglong2 vb0 = wB2[0];
    FMA2(a0, va0.x, Epk[0]); FMA2(a1, va0.y, Epk[1]);
    FMA2(b0, vb0.x, Epk[0]); FMA2(b1, vb0.y, Epk[1]);
#pragma unroll
    for (int k = 1; k < 12; k++) {
        ulonglong2 va = wA2[k];
        ulonglong2 vb = wB2[k];
        FMA2(a0, va.x, Epk[2 * k]); FMA2(a1, va.y, Epk[2 * k + 1]);
        FMA2(b0, vb.x, Epk[2 * k]); FMA2(b1, vb.y, Epk[2 * k + 1]);
    }
    unsigned long long as, bs;
    ADD2(as, a0, a1); ADD2(bs, b0, b1);
    float alo, ahi, blo, bhi;
    UNPK2(alo, ahi, as); UNPK2(blo, bhi, bs);
    unsigned int eA = ((unsigned int)va0.x) >> 23;
    unsigned int eB = ((unsigned int)vb0.x) >> 23;
    CexpA += (int)eA - 127;
    CexpB += (int)eB - 127;
    float sA = __uint_as_float((254u - eA) << 23);
    float sB = __uint_as_float((254u - eB) << 23);
    oA[j] = (alo + ahi) * (emA * sA);
    oB[j] = (blo + bhi) * (emB * sB);
}

// Grid layout (blockDim 48x2 = 96 threads, 3 full warps, zero lane padding):
//   [0, 256)       mode 0 (time axis):  4 sids/block (2 groups x 2 seqs)
//   [256, 2304)    mode 1 (level axis): 2 jobs x 8 sids -> 2048 blocks = 32768 sids
//   [2304, 4352)   mode 2 (rolled):     2 jobs x 8 sids -> 2048 blocks = 32768 sids
// All sids in a block share one p (mode 0) / one t (modes 1/2) -> uniform len.
__global__ __launch_bounds__(NS * GRP, 6) void crf_fwd_kernel(
    const float* __restrict__ logits,
    const float* __restrict__ trT,
    const float* __restrict__ trL,
    const float* __restrict__ trR,
    const int*   __restrict__ tags)
{
    __shared__ Smem sm;
    const int j = threadIdx.x;           // state 0..47
    const int g = threadIdx.y;           // group in block
    const int tid = g * NS + j;

    const int bid = blockIdx.x;
    int mode, mbase;
    const float* traw;
    float* outp;
    if (bid < 256)       { mode = 0; mbase = bid;                traw = trT; outp = g_llT; }
    else if (bid < 2304) { mode = 1; mbase = (bid - 256) * 2;    traw = trL; outp = g_llL; }
    else                 { mode = 2; mbase = (bid - 2304) * 2;   traw = trR; outp = g_llR; }

    // trans -> smem (coalesced), build Epk; modes 1/2 then reuse that smem.
    for (int k = tid; k < NS2; k += NS * GRP) sm.trans[k] = traw[k];
    __syncthreads();
    unsigned long long Epk[NS / 2];
#pragma unroll
    for (int k = 0; k < NS / 2; k++) {
        float lo = __expf(sm.trans[(2 * k) * NS + j]);
        float hi = __expf(sm.trans[(2 * k + 1) * NS + j]);
        PACK2(Epk[k], lo, hi);
    }
    __syncthreads();

    if (mode == 0) {
        // ---- mode 0: 2 seqs per group; prefetch ring carries exp(emit) ----
        const int sidA = 4 * mbase + 2 * g;
        const int p = sidA >> 6;
        const int len = T_DIM - p;
        const int baseA = sidA * (T_DIM * NS);
        const int baseB = baseA + T_DIM * NS;
        const int* tgA = tags + sidA * T_DIM;
        const int* tgB = tgA + T_DIM;

        float spA = 0.f, spB = 0.f;
        for (int t = j; t < len; t += NS) {
            int a0 = tgA[t];
            int b0 = tgB[t];
            spA += logits[baseA + t * NS + a0];
            spB += logits[baseB + t * NS + b0];
            if (t + 1 < len) {
                spA += sm.trans[a0 * NS + tgA[t + 1]];
                spB += sm.trans[b0 * NS + tgB[t + 1]];
            }
        }

        const float* epA = logits + baseA + j;
        const float* epB = logits + baseB + j;
        sm.u[0][g][0][j] = __expf(epA[0]);
        sm.u[0][g][1][j] = __expf(epB[0]);

        float cA[4], cB[4];                 // ring holds exp(emit)
#pragma unroll
        for (int k = 0; k < 4; k++) {
            int tl = min(1 + k, len - 1);
            cA[k] = __expf(epA[tl * NS]);
            cB[k] = __expf(epB[tl * NS]);
        }
        int CexpA = 0, CexpB = 0, cur = 0;
        __syncthreads();

        for (int t0 = 1; t0 < len; t0 += 4) {
            float nA[4], nB[4];
#pragma unroll
            for (int k = 0; k < 4; k++) {
                int tl = min(t0 + 4 + k, len - 1);
                nA[k] = __expf(epA[tl * NS]);   // MUFU in MLP-rich prefetch, not in chain
                nB[k] = __expf(epB[tl * NS]);
            }
#pragma unroll
            for (int k = 0; k < 4; k++) {
                if (t0 + k < len) {   // block-uniform predicate
                    crf_step2(sm.u[cur][g][0], sm.u[cur][g][1],
                              sm.u[cur ^ 1][g][0], sm.u[cur ^ 1][g][1],
                              Epk, cA[k], cB[k], j, CexpA, CexpB);
                    __syncthreads();
                    cur ^= 1;
                }
            }
#pragma unroll
            for (int k = 0; k < 4; k++) { cA[k] = nA[k]; cB[k] = nB[k]; }
        }

        sm.sc[g][0][j] = spA;
        sm.sc[g][1][j] = spB;
        __syncthreads();
        if (j < 16) {
            sm.sc[g][0][j] += sm.sc[g][0][j + 16] + sm.sc[g][0][j + 32];
            sm.sc[g][1][j] += sm.sc[g][1][j + 16] + sm.sc[g][1][j + 32];
            float* uA = sm.u[cur][g][0];
            float* uB = sm.u[cur][g][1];
            uA[j] += uA[j + 16] + uA[j + 32];
            uB[j] += uB[j + 16] + uB[j + 32];
        }
        __syncthreads();
        if (j < 2) {
            const float* uf = sm.u[cur][g][j];
            const float* sf = sm.sc[g][j];
            float su = 0.f, sc = 0.f;
#pragma unroll
            for (int i = 0; i < 16; i++) { su += uf[i]; sc += sf[i]; }
            int Ce = (j == 0) ? CexpA : CexpB;
            outp[sidA + j] = (float)((double)sc - ((double)logf(su) + (double)Ce * LN2));
        }
        return;
    }

    // ---- modes 1/2: 4 seqs per group, 2 jobs of 8 sids ----
    const int SEQ_STRIDE = T_DIM * NS;
    for (int it = 0; it < 2; ++it) {
        const int m    = mbase + it;          // job: sids 8m .. 8m+7
        const int sid0 = 8 * m;
        const int t    = sid0 >> 6;           // uniform across the 8 sids
        int estride, tstride, len;
        if (mode == 1) {
            estride = B_DIM * T_DIM * NS;
            tstride = B_DIM * T_DIM;
            len     = min(P_LVL, T_DIM - t);
        } else {
            estride = B_DIM * T_DIM * NS - NS;
            tstride = B_DIM * T_DIM - 1;
            len     = min(P_LVL, t + 1);
        }
        const int b0    = (sid0 & 63) + 4 * g;             // first b of this group
        const int baseG = (b0 * T_DIM + t) * NS;           // seq s -> baseG + s*SEQ_STRIDE

        // stage exp(emissions) (own state) for 4 seqs: 64 LDGs in flight/lane,
        // MUFU applied here (MLP-rich) so the step loop has none.
#pragma unroll
        for (int s = 0; s < 4; s++) {
#pragma unroll
            for (int k = 0; k < P_LVL; k++) {
                int kk = min(k, len - 1);
                sm.em[g][s][k][j] = __expf(logits[baseG + s * SEQ_STRIDE + kk * estride + j]);
            }
        }

        // score phase: 128 slots (8 seqs x 16 steps) over 96 threads, 2 rounds
#pragma unroll
        for (int r = 0; r < 2; r++) {
            int slot = tid + r * 96;
            if (slot < 128) {
                int sl = slot >> 4;        // local sid 0..7
                int tt = slot & 15;
                float sp = 0.f;
                if (tt < len) {
                    int bb = (sid0 & 63) + sl;
                    int tb = bb * T_DIM + t;
                    int eb = (bb * T_DIM + t) * NS;
                    int tg0 = tags[tb + tt * tstride];
                    sp = logits[eb + tt * estride + tg0];
                    if (tt + 1 < len) {
                        int tg1 = tags[tb + (tt + 1) * tstride];
                        sp += traw[tg0 * NS + tg1];   // L2-cached gather
                    }
                }
                sm.sc[sl >> 2][sl & 3][tt] = sp;
            }
        }

        // init alpha (em already exponentiated)
#pragma unroll
        for (int s = 0; s < 4; s++)
            sm.u[0][g][s][j] = sm.em[g][s][0][j];

        int Cexp[4] = {0, 0, 0, 0};
        int cur = 0;
        __syncthreads();

        for (int tt = 1; tt < len; tt++) {
            unsigned long long acc0[4], acc1[4];
            unsigned int ue[4];
#pragma unroll
            for (int s = 0; s < 4; s++) {
                const ulonglong2* w2 = reinterpret_cast<const ulonglong2*>(sm.u[cur][g][s]);
                unsigned long long a0 = 0ull, a1 = 0ull;
                ulonglong2 v0 = w2[0];
                ue[s] = ((unsigned int)v0.x) >> 23;
                FMA2(a0, v0.x, Epk[0]); FMA2(a1, v0.y, Epk[1]);
#pragma unroll
                for (int k = 1; k < 12; k++) {
                    ulonglong2 v = w2[k];
                    FMA2(a0, v.x, Epk[2 * k]); FMA2(a1, v.y, Epk[2 * k + 1]);
                }
                acc0[s] = a0; acc1[s] = a1;
            }
#pragma unroll
            for (int s = 0; s < 4; s++) {
                unsigned long long as;
                ADD2(as, acc0[s], acc1[s]);
                float lo, hi;
                UNPK2(lo, hi, as);
                Cexp[s] += (int)ue[s] - 127;
                float sscl = __uint_as_float((254u - ue[s]) << 23);
                sm.u[cur ^ 1][g][s][j] = (lo + hi) * (sm.em[g][s][tt][j] * sscl);
            }
            __syncthreads();       // one barrier per 4 seq-steps
            cur ^= 1;
        }

        __syncthreads();   // covers len==1 (score writes -> epilogue reads)
#pragma unroll
        for (int s = 0; s < 4; s++)
            if (j < 16) {
                float* uu = sm.u[cur][g][s];
                uu[j] += uu[j + 16] + uu[j + 32];
            }
        __syncthreads();
        if (j < 4) {
            const int s = j;
            const float* uf = sm.u[cur][g][s];
            const float* sf = sm.sc[g][s];
            float su = 0.f, sc = 0.f;
#pragma unroll
            for (int i = 0; i < 16; i++) { su += uf[i]; sc += sf[i]; }
            outp[sid0 + 4 * g + s] =
                (float)((double)sc - ((double)logf(su) + (double)Cexp[s] * LN2));
        }
        __syncthreads();   // protect smem reuse by next job
    }
}

// Deterministic reduction: fp32 partial chains (FP64 rt is the bottleneck
// otherwise), double only in the fixed 256-wide tree.
__global__ void reduce_kernel(float* __restrict__ out) {
    __shared__ double sd[256];
    const int which = blockIdx.x;
    const float* src = (which == 0) ? g_llT : (which == 1) ? g_llL : g_llR;
    const int n4 = ((which == 0) ? (P_LVL * B_DIM) : (T_DIM * B_DIM)) / 4;
    const float4* s4 = reinterpret_cast<const float4*>(src);
    float a0 = 0.f, a1 = 0.f, a2 = 0.f, a3 = 0.f;
    for (int i = threadIdx.x; i < n4; i += 256) {
        float4 v = s4[i];
        a0 += v.x; a1 += v.y; a2 += v.z; a3 += v.w;
    }
    sd[threadIdx.x] = (double)(a0 + a1) + (double)(a2 + a3);
    __syncthreads();
    for (int s = 128; s > 0; s >>= 1) {
        if (threadIdx.x < s) sd[threadIdx.x] += sd[threadIdx.x + s];
        __syncthreads();
    }
    if (threadIdx.x == 0) out[which] = (float)(-sd[0]);
}

extern "C" void kernel_launch(void* const* d_in, const int* in_sizes, int n_in,
                              void* d_out, int out_size) {
    const float* logits = (const float*)d_in[0];
    const float* trT    = (const float*)d_in[1];
    const float* trL    = (const float*)d_in[2];
    const float* trR    = (const float*)d_in[3];
    const int*   tags   = (const int*)d_in[4];
    // d_in[5] = mask: analytic (t < T - p), not read.

    dim3 blk(NS, GRP);
    crf_fwd_kernel<<<256 + 2048 + 2048, blk>>>(logits, trT, trL, trR, tags);

    reduce_kernel<<<3, 256>>>((float*)d_out);
}

// round 14
// speedup vs baseline: 1.1512x; 1.0045x over previous
#include <cuda_runtime.h>
#include <cuda_bf16.h>

#define P_LVL 16
#define B_DIM 64
#define T_DIM 512
#define NS 48
#define NS2 (NS*NS)
#define GRP 2
#define LN2 0.6931471805599453

// ---- packed f32x2 helpers (FFMA2 path, PTX-only per SASS_QUICKREF) ----
#define FMA2(acc, a, b) asm("fma.rn.f32x2 %0, %1, %2, %0;" : "+l"(acc) : "l"(a), "l"(b))
#define ADD2(d, a, b)   asm("add.rn.f32x2 %0, %1, %2;"      : "=l"(d)  : "l"(a), "l"(b))
#define PACK2(d, lo, hi) asm("mov.b64 %0, {%1, %2};"        : "=l"(d)  : "f"(lo), "f"(hi))
#define UNPK2(lo, hi, v) asm("mov.b64 {%0, %1}, %2;"        : "=f"(lo), "=f"(hi) : "l"(v))

__device__ __align__(16) float g_llT[P_LVL * B_DIM];   // 1024
__device__ __align__(16) float g_llL[T_DIM * B_DIM];   // 32768
__device__ __align__(16) float g_llR[T_DIM * B_DIM];   // 32768

struct Smem {
    union {
        float trans[NS2];                        // mode 0: persistent (score gathers)
        __nv_bfloat16 em[GRP][8][P_LVL][NS];     // modes 1/2: staged exp(emit), bf16
    };
    float u[2][GRP][8][NS];                      // double-buffered alpha (mode 0 uses [..][0..1])
    union {
        float m0[GRP][2][NS];                    // mode 0 score partials
        float m12[GRP][8][P_LVL];                // modes 1/2 per-step scores
    } sc;
};

// 2-seq step (mode 0). Lane j owns state j; power-of-two renorm by u0.
// emA/emB are PRE-EXPONENTIATED emissions.
__device__ __forceinline__ void crf_step2(
    const float* __restrict__ wA, const float* __restrict__ wB,
    float* __restrict__ oA, float* __restrict__ oB,
    const unsigned long long* __restrict__ Epk,
    float emA, float emB, int j, int& CexpA, int& CexpB)
{
    const ulonglong2* wA2 = reinterpret_cast<const ulonglong2*>(wA);
    const ulonglong2* wB2 = reinterpret_cast<const ulonglong2*>(wB);
    unsigned long long a0 = 0ull, a1 = 0ull, b0 = 0ull, b1 = 0ull;
    ulonglong2 va0 = wA2[0];
    ulonglong2 vb0 = wB2[0];
    FMA2(a0, va0.x, Epk[0]); FMA2(a1, va0.y, Epk[1]);
    FMA2(b0, vb0.x, Epk[0]); FMA2(b1, vb0.y, Epk[1]);
#pragma unroll
    for (int k = 1; k < 12; k++) {
        ulonglong2 va = wA2[k];
        ulonglong2 vb = wB2[k];
        FMA2(a0, va.x, Epk[2 * k]); FMA2(a1, va.y, Epk[2 * k + 1]);
        FMA2(b0, vb.x, Epk[2 * k]); FMA2(b1, vb.y, Epk[2 * k + 1]);
    }
    unsigned long long as, bs;
    ADD2(as, a0, a1); ADD2(bs, b0, b1);
    float alo, ahi, blo, bhi;
    UNPK2(alo, ahi, as); UNPK2(blo, bhi, bs);
    unsigned int eA = ((unsigned int)va0.x) >> 23;
    unsigned int eB = ((unsigned int)vb0.x) >> 23;
    CexpA += (int)eA - 127;
    CexpB += (int)eB - 127;
    float sA = __uint_as_float((254u - eA) << 23);
    float sB = __uint_as_float((254u - eB) << 23);
    oA[j] = (alo + ahi) * (emA * sA);
    oB[j] = (blo + bhi) * (emB * sB);
}

// Grid layout (blockDim 48x2 = 96 threads, 3 full warps):
//   [0, 256)       mode 0 (time axis):  4 sids/block (2 groups x 2 seqs)
//   [256, 1280)    mode 1 (level axis): 2 jobs x 16 sids (2 groups x 8 seqs)
//   [1280, 2304)   mode 2 (rolled):     2 jobs x 16 sids
// All sids in a block share one p (mode 0) / one t (modes 1/2) -> uniform len.
__global__ __launch_bounds__(NS * GRP, 6) void crf_fwd_kernel(
    const float* __restrict__ logits,
    const float* __restrict__ trT,
    const float* __restrict__ trL,
    const float* __restrict__ trR,
    const int*   __restrict__ tags)
{
    __shared__ Smem sm;
    const int j = threadIdx.x;           // state 0..47
    const int g = threadIdx.y;           // group in block
    const int tid = g * NS + j;

    const int bid = blockIdx.x;
    int mode, mbase;
    const float* traw;
    float* outp;
    if (bid < 256)       { mode = 0; mbase = bid;                traw = trT; outp = g_llT; }
    else if (bid < 1280) { mode = 1; mbase = (bid - 256) * 2;    traw = trL; outp = g_llL; }
    else                 { mode = 2; mbase = (bid - 1280) * 2;   traw = trR; outp = g_llR; }

    // trans -> smem (coalesced), build Epk; modes 1/2 then reuse that smem.
    for (int k = tid; k < NS2; k += NS * GRP) sm.trans[k] = traw[k];
    __syncthreads();
    unsigned long long Epk[NS / 2];
#pragma unroll
    for (int k = 0; k < NS / 2; k++) {
        float lo = __expf(sm.trans[(2 * k) * NS + j]);
        float hi = __expf(sm.trans[(2 * k + 1) * NS + j]);
        PACK2(Epk[k], lo, hi);
    }
    __syncthreads();

    if (mode == 0) {
        // ---- mode 0: 2 seqs per group; prefetch ring carries exp(emit) ----
        const int sidA = 4 * mbase + 2 * g;
        const int p = sidA >> 6;
        const int len = T_DIM - p;
        const int baseA = sidA * (T_DIM * NS);
        const int baseB = baseA + T_DIM * NS;
        const int* tgA = tags + sidA * T_DIM;
        const int* tgB = tgA + T_DIM;

        float spA = 0.f, spB = 0.f;
        for (int t = j; t < len; t += NS) {
            int a0 = tgA[t];
            int b0 = tgB[t];
            spA += logits[baseA + t * NS + a0];
            spB += logits[baseB + t * NS + b0];
            if (t + 1 < len) {
                spA += sm.trans[a0 * NS + tgA[t + 1]];
                spB += sm.trans[b0 * NS + tgB[t + 1]];
            }
        }

        const float* epA = logits + baseA + j;
        const float* epB = logits + baseB + j;
        sm.u[0][g][0][j] = __expf(epA[0]);
        sm.u[0][g][1][j] = __expf(epB[0]);

        float cA[4], cB[4];                 // ring holds exp(emit)
#pragma unroll
        for (int k = 0; k < 4; k++) {
            int tl = min(1 + k, len - 1);
            cA[k] = __expf(epA[tl * NS]);
            cB[k] = __expf(epB[tl * NS]);
        }
        int CexpA = 0, CexpB = 0, cur = 0;
        __syncthreads();

        for (int t0 = 1; t0 < len; t0 += 4) {
            float nA[4], nB[4];
#pragma unroll
            for (int k = 0; k < 4; k++) {
                int tl = min(t0 + 4 + k, len - 1);
                nA[k] = __expf(epA[tl * NS]);
                nB[k] = __expf(epB[tl * NS]);
            }
#pragma unroll
            for (int k = 0; k < 4; k++) {
                if (t0 + k < len) {   // block-uniform predicate
                    crf_step2(sm.u[cur][g][0], sm.u[cur][g][1],
                              sm.u[cur ^ 1][g][0], sm.u[cur ^ 1][g][1],
                              Epk, cA[k], cB[k], j, CexpA, CexpB);
                    __syncthreads();
                    cur ^= 1;
                }
            }
#pragma unroll
            for (int k = 0; k < 4; k++) { cA[k] = nA[k]; cB[k] = nB[k]; }
        }

        sm.sc.m0[g][0][j] = spA;
        sm.sc.m0[g][1][j] = spB;
        __syncthreads();
        if (j < 16) {
            sm.sc.m0[g][0][j] += sm.sc.m0[g][0][j + 16] + sm.sc.m0[g][0][j + 32];
            sm.sc.m0[g][1][j] += sm.sc.m0[g][1][j + 16] + sm.sc.m0[g][1][j + 32];
            float* uA = sm.u[cur][g][0];
            float* uB = sm.u[cur][g][1];
            uA[j] += uA[j + 16] + uA[j + 32];
            uB[j] += uB[j + 16] + uB[j + 32];
        }
        __syncthreads();
        if (j < 2) {
            const float* uf = sm.u[cur][g][j];
            const float* sf = sm.sc.m0[g][j];
            float su = 0.f, sc = 0.f;
#pragma unroll
            for (int i = 0; i < 16; i++) { su += uf[i]; sc += sf[i]; }
            int Ce = (j == 0) ? CexpA : CexpB;
            outp[sidA + j] = (float)((double)sc - ((double)logf(su) + (double)Ce * LN2));
        }
        return;
    }

    // ---- modes 1/2: 8 seqs per group, 2 jobs of 16 sids ----
    const int SEQ_STRIDE = T_DIM * NS;
    for (int it = 0; it < 2; ++it) {
        const int m    = mbase + it;          // job: sids 16m .. 16m+15
        const int sid0 = 16 * m;
        const int t    = sid0 >> 6;           // uniform across the 16 sids
        int estride, tstride, len;
        if (mode == 1) {
            estride = B_DIM * T_DIM * NS;
            tstride = B_DIM * T_DIM;
            len     = min(P_LVL, T_DIM - t);
        } else {
            estride = B_DIM * T_DIM * NS - NS;
            tstride = B_DIM * T_DIM - 1;
            len     = min(P_LVL, t + 1);
        }
        const int b0    = (sid0 & 63) + 8 * g;             // first b of this group
        const int baseG = (b0 * T_DIM + t) * NS;           // seq s -> baseG + s*SEQ_STRIDE

        // stage exp(emissions) (own state) for 8 seqs as bf16: 128 LDGs in
        // flight per lane; MUFU+cvt here (MLP-rich), none in the step loop.
#pragma unroll
        for (int s = 0; s < 8; s++) {
#pragma unroll
            for (int k = 0; k < P_LVL; k++) {
                int kk = min(k, len - 1);
                sm.em[g][s][k][j] =
                    __float2bfloat16(__expf(logits[baseG + s * SEQ_STRIDE + kk * estride + j]));
            }
        }

        // score phase: 256 slots (16 seqs x 16 steps) over 96 threads, 3 rounds
#pragma unroll
        for (int r = 0; r < 3; r++) {
            int slot = tid + r * 96;
            if (slot < 256) {
                int sl = slot >> 4;        // local sid 0..15
                int tt = slot & 15;
                float sp = 0.f;
                if (tt < len) {
                    int bb = (sid0 & 63) + sl;
                    int tb = bb * T_DIM + t;
                    int eb = (bb * T_DIM + t) * NS;
                    int tg0 = tags[tb + tt * tstride];
                    sp = logits[eb + tt * estride + tg0];
                    if (tt + 1 < len) {
                        int tg1 = tags[tb + (tt + 1) * tstride];
                        sp += traw[tg0 * NS + tg1];   // L2-cached gather
                    }
                }
                sm.sc.m12[sl >> 3][sl & 7][tt] = sp;
            }
        }

        // init alpha from staged exp(emit)
#pragma unroll
        for (int s = 0; s < 8; s++)
            sm.u[0][g][s][j] = __bfloat162float(sm.em[g][s][0][j]);

        int Cexp[8] = {0, 0, 0, 0, 0, 0, 0, 0};
        int cur = 0;
        __syncthreads();

        for (int tt = 1; tt < len; tt++) {
#pragma unroll
            for (int h = 0; h < 2; h++) {        // two 4-seq sub-batches
                unsigned long long acc0[4], acc1[4];
                unsigned int ue[4];
                float emv[4];
#pragma unroll
                for (int q = 0; q < 4; q++) {
                    const int s = 4 * h + q;
                    emv[q] = __bfloat162float(sm.em[g][s][tt][j]);
                    const ulonglong2* w2 = reinterpret_cast<const ulonglong2*>(sm.u[cur][g][s]);
                    unsigned long long a0 = 0ull, a1 = 0ull;
                    ulonglong2 v0 = w2[0];
                    ue[q] = ((unsigned int)v0.x) >> 23;
                    FMA2(a0, v0.x, Epk[0]); FMA2(a1, v0.y, Epk[1]);
#pragma unroll
                    for (int k = 1; k < 12; k++) {
                        ulonglong2 v = w2[k];
                        FMA2(a0, v.x, Epk[2 * k]); FMA2(a1, v.y, Epk[2 * k + 1]);
                    }
                    acc0[q] = a0; acc1[q] = a1;
                }
#pragma unroll
                for (int q = 0; q < 4; q++) {
                    const int s = 4 * h + q;
                    unsigned long long as;
                    ADD2(as, acc0[q], acc1[q]);
                    float lo, hi;
                    UNPK2(lo, hi, as);
                    Cexp[s] += (int)ue[q] - 127;
                    float sscl = __uint_as_float((254u - ue[q]) << 23);
                    sm.u[cur ^ 1][g][s][j] = (lo + hi) * (emv[q] * sscl);
                }
            }
            __syncthreads();       // one barrier per 8 seq-steps
            cur ^= 1;
        }

        __syncthreads();   // covers len==1 (score writes -> epilogue reads)
#pragma unroll
        for (int s = 0; s < 8; s++)
            if (j < 16) {
                float* uu = sm.u[cur][g][s];
                uu[j] += uu[j + 16] + uu[j + 32];
            }
        __syncthreads();
        if (j < 8) {
            const int s = j;
            const float* uf = sm.u[cur][g][s];
            const float* sf = sm.sc.m12[g][s];
            float su = 0.f, sc = 0.f;
#pragma unroll
            for (int i = 0; i < 16; i++) { su += uf[i]; sc += sf[i]; }
            outp[sid0 + 8 * g + s] =
                (float)((double)sc - ((double)logf(su) + (double)Cexp[s] * LN2));
        }
        __syncthreads();   // protect smem reuse by next job
    }
}

// Deterministic reduction: fp32 partial chains, double only in the fixed
// 1024-wide tree (FP64 rt would bottleneck otherwise).
__global__ void reduce_kernel(float* __restrict__ out) {
    __shared__ double sd[1024];
    const int which = blockIdx.x;
    const float* src = (which == 0) ? g_llT : (which == 1) ? g_llL : g_llR;
    const int n4 = ((which == 0) ? (P_LVL * B_DIM) : (T_DIM * B_DIM)) / 4;
    const float4* s4 = reinterpret_cast<const float4*>(src);
    float a0 = 0.f, a1 = 0.f, a2 = 0.f, a3 = 0.f;
    for (int i = threadIdx.x; i < n4; i += 1024) {
        float4 v = s4[i];
        a0 += v.x; a1 += v.y; a2 += v.z; a3 += v.w;
    }
    sd[threadIdx.x] = (double)(a0 + a1) + (double)(a2 + a3);
    __syncthreads();
    for (int s = 512; s > 0; s >>= 1) {
        if (threadIdx.x < s) sd[threadIdx.x] += sd[threadIdx.x + s];
        __syncthreads();
    }
    if (threadIdx.x == 0) out[which] = (float)(-sd[0]);
}

extern "C" void kernel_launch(void* const* d_in, const int* in_sizes, int n_in,
                              void* d_out, int out_size) {
    const float* logits = (const float*)d_in[0];
    const float* trT    = (const float*)d_in[1];
    const float* trL    = (const float*)d_in[2];
    const float* trR    = (const float*)d_in[3];
    const int*   tags   = (const int*)d_in[4];
    // d_in[5] = mask: analytic (t < T - p), not read.

    dim3 blk(NS, GRP);
    crf_fwd_kernel<<<256 + 1024 + 1024, blk>>>(logits, trT, trL, trR, tags);

    reduce_kernel<<<3, 1024>>>((float*)d_out);
}